// round 6
// baseline (speedup 1.0000x reference)
#include <cuda_runtime.h>
#include <cuda_bf16.h>
#include <cstdint>

// BlockedF8Linear: out[m,n] = sum_k x[m,k]*(w[n,k]*scale[n/128,k/128]) + bias[n]
// M = B*S = 4096, N = 4096, K = 4096.
//
// Primary (featured pass only): tcgen05 bf16 SS MMA, scale folded into x,
// x*s split hi+lo bf16 (w exact e4m3 -> exact bf16), fp32 TMEM accumulator.
// R5 de-risk vs crashed R2/R4: single buffer, ONE mbarrier, commit+wait every
// chunk (no cross-chunk outstanding MMA), runtime 1024B-aligned operand base,
// register prefetch for overlap, no relinquish, mbarrier inval at end.
// Fallback: proven R3 tf32 mma.sync kernel (887us), self-gated on g_tc_flag.
// (R6 = identical resubmit of R5; R5 never ran — GPU broker timeout.)

#define KDIM 4096
#define NDIM 4096
#define MDIM 4096

#if defined(__CUDA_ARCH_FEAT_SM103_ALL) || defined(__CUDA_ARCH_FEAT_SM100_ALL)
#define TC_FEAT 1
#else
#define TC_FEAT 0
#endif

__device__ int g_tc_flag;

__global__ void f8lin_probe() {
#if TC_FEAT
    g_tc_flag = 1;
#else
    g_tc_flag = 0;
#endif
}

// ======================= tcgen05 path =======================

#define TM 128
#define TN 128
#define KC 64                        // one SW128 row of bf16 per chunk
#define NCHUNKS (KDIM / KC)          // 64
#define MAT_BYTES (TM * 128)         // 16384 per bf16 tile
#define SMEM_BYTES (1024 + 1024 + 3 * MAT_BYTES)   // hdr + align pad + 48K

#define SWZ(b) ((b) ^ (((b) >> 3) & 0x70))

static __device__ __forceinline__ uint32_t smem_u32(const void* p) {
    uint32_t a;
    asm("{ .reg .u64 t; cvta.to.shared.u64 t, %1; cvt.u32.u64 %0, t; }"
        : "=r"(a) : "l"(p));
    return a;
}

#if TC_FEAT

// idesc kind::f16: dtype=F32(1<<4) atype=BF16(1<<7) btype=BF16(1<<10)
// N/8<<17 M/16<<24
static constexpr uint32_t IDESC =
    (1u << 4) | (1u << 7) | (1u << 10) | ((TN / 8u) << 17) | ((TM / 16u) << 24);

// SW128 K-major: layout=2, version=1, SBO=64, LBO=1
static constexpr uint64_t DESC_BASE =
    (uint64_t(2) << 61) | (uint64_t(1) << 46) | (uint64_t(64) << 32) | (uint64_t(1) << 16);
#define MKDESC(addr) (DESC_BASE | ((uint64_t)((addr) >> 4) & 0x3FFF))

static __device__ __forceinline__ uint32_t elect1() {
    uint32_t p;
    asm volatile(
        "{\n\t.reg .pred p;\n\t"
        "elect.sync _|p, 0xFFFFFFFF;\n\t"
        "selp.b32 %0, 1, 0, p;\n\t}"
        : "=r"(p));
    return p;
}

#define MBARRIER_INIT(addr, cnt) \
    asm volatile("mbarrier.init.shared.b64 [%0], %1;" :: "r"(addr), "r"(cnt) : "memory")
#define MBARRIER_INVAL(addr) \
    asm volatile("mbarrier.inval.shared.b64 [%0];" :: "r"(addr) : "memory")

#define MBARRIER_WAIT_PARITY(mbar_addr, parity) do {                                   \
    uint32_t _mbar = (uint32_t)(mbar_addr);                                            \
    uint32_t _par = (uint32_t)(parity);                                                \
    asm volatile(                                                                      \
        "{\n\t.reg .pred P1;\n\t"                                                      \
        "WAIT_LOOP_%=:\n\t"                                                            \
        "mbarrier.try_wait.parity.acquire.cta.shared::cta.b64 P1, [%0], %1, 0x989680;\n\t" \
        "@P1 bra.uni WAIT_DONE_%=;\n\t"                                                \
        "bra.uni WAIT_LOOP_%=;\n\t"                                                    \
        "WAIT_DONE_%=:\n\t}"                                                           \
        :: "r"(_mbar), "r"(_par) : "memory");                                          \
} while (0)

#define TCGEN05_ALLOC(sa, n) \
    asm volatile("tcgen05.alloc.cta_group::1.sync.aligned.shared::cta.b32 [%0], %1;" \
                 :: "r"((uint32_t)(sa)), "r"((uint32_t)(n)) : "memory")
#define TCGEN05_DEALLOC(tm, n) \
    asm volatile("tcgen05.dealloc.cta_group::1.sync.aligned.b32 %0, %1;" :: "r"(tm), "r"(n))
#define TCGEN05_COMMIT(mbar) \
    asm volatile("tcgen05.commit.cta_group::1.mbarrier::arrive::one.shared::cluster.b64 [%0];" \
                 :: "r"((uint32_t)(mbar)) : "memory")
#define TCGEN05_FENCE_AFTER() \
    asm volatile("tcgen05.fence::after_thread_sync;" ::: "memory")
#define TCGEN05_WAIT_LD() \
    asm volatile("tcgen05.wait::ld.sync.aligned;" ::: "memory")
#define FENCE_ASYNC_SHARED() \
    asm volatile("fence.proxy.async.shared::cta;" ::: "memory")

#define STS128(addr, r0, r1, r2, r3) \
    asm volatile("st.shared.v4.b32 [%0], {%1, %2, %3, %4};" \
                 :: "r"(addr), "r"(r0), "r"(r1), "r"(r2), "r"(r3) : "memory")

#define TCGEN05_LD_32X32B_X32(r, tmem_addr) \
    asm volatile( \
        "tcgen05.ld.sync.aligned.32x32b.x32.b32 " \
        "{%0, %1, %2, %3, %4, %5, %6, %7, " \
        " %8, %9, %10, %11, %12, %13, %14, %15, " \
        " %16, %17, %18, %19, %20, %21, %22, %23, " \
        " %24, %25, %26, %27, %28, %29, %30, %31}, [%32];" \
        : "=r"((r)[0]),  "=r"((r)[1]),  "=r"((r)[2]),  "=r"((r)[3]), \
          "=r"((r)[4]),  "=r"((r)[5]),  "=r"((r)[6]),  "=r"((r)[7]), \
          "=r"((r)[8]),  "=r"((r)[9]),  "=r"((r)[10]), "=r"((r)[11]), \
          "=r"((r)[12]), "=r"((r)[13]), "=r"((r)[14]), "=r"((r)[15]), \
          "=r"((r)[16]), "=r"((r)[17]), "=r"((r)[18]), "=r"((r)[19]), \
          "=r"((r)[20]), "=r"((r)[21]), "=r"((r)[22]), "=r"((r)[23]), \
          "=r"((r)[24]), "=r"((r)[25]), "=r"((r)[26]), "=r"((r)[27]), \
          "=r"((r)[28]), "=r"((r)[29]), "=r"((r)[30]), "=r"((r)[31]) \
        : "r"(tmem_addr))

static __device__ __forceinline__ void mma_f16_ss(
    uint32_t d_tmem, uint64_t a_desc, uint64_t b_desc, uint32_t idesc, bool acc) {
    uint32_t en = acc ? 1u : 0u;
    asm volatile(
        "{\n\t.reg .pred p;\n\t"
        "setp.ne.u32 p, %5, 0;\n\t"
        "tcgen05.mma.cta_group::1.kind::f16 [%0], %1, %2, %3, {%4, %4, %4, %4}, p;\n\t}"
        :: "r"(d_tmem), "l"(a_desc), "l"(b_desc), "r"(idesc), "r"(0u), "r"(en)
        : "memory");
}

static __device__ __forceinline__ void split2(float v0, float v1, uint32_t& hi, uint32_t& lo) {
    __nv_bfloat162 h = __floats2bfloat162_rn(v0, v1);
    float r0 = v0 - __bfloat162float(h.x);
    float r1 = v1 - __bfloat162float(h.y);
    __nv_bfloat162 l = __floats2bfloat162_rn(r0, r1);
    hi = *reinterpret_cast<uint32_t*>(&h);
    lo = *reinterpret_cast<uint32_t*>(&l);
}

static __device__ __forceinline__ uint32_t pack_bf16x2(float v0, float v1) {
    __nv_bfloat162 h = __floats2bfloat162_rn(v0, v1);
    return *reinterpret_cast<uint32_t*>(&h);
}

#endif  // TC_FEAT

extern "C" __global__ void __launch_bounds__(256) __cluster_dims__(1, 1, 1)
f8lin_tcgen05(const float* __restrict__ x, const float* __restrict__ w,
              const float* __restrict__ sinv, const float* __restrict__ bias,
              float* __restrict__ out) {
#if TC_FEAT
    extern __shared__ char smem[];
    const uint32_t smem_base = smem_u32(smem);
    const int tid = threadIdx.x;
    const int wid = tid >> 5;
    const int lid = tid & 31;

    const int n0 = blockIdx.x * TN;
    const int m0 = blockIdx.y * TM;

    const uint32_t mbar = smem_base + 8;
    // 1024B-aligned operand base (SW128 descriptor requirement)
    const uint32_t buf = (smem_base + 1024 + 1023) & ~1023u;
    const uint32_t xhi = buf;
    const uint32_t xlo = buf + MAT_BYTES;
    const uint32_t wbf = buf + 2 * MAT_BYTES;

    if (wid == 0) {
        TCGEN05_ALLOC(smem_base, 128);
    }
    if (tid == 0) {
        MBARRIER_INIT(mbar, 1);
    }
    __syncthreads();
    uint32_t tmem_base;
    asm volatile("ld.shared.b32 %0, [%1];" : "=r"(tmem_base) : "r"(smem_base));

    // producer mapping: row = tid>>1 (0..127), k-half h = tid&1 (32 elems)
    const int row = tid >> 1;
    const int h = tid & 1;
    const float* xrow = x + (size_t)(m0 + row) * KDIM + h * 32;
    const float* wrow = w + (size_t)(n0 + row) * KDIM + h * 32;
    const uint32_t rowb = (uint32_t)row * 128 + (uint32_t)h * 64;

    const uint64_t ah = MKDESC(xhi);
    const uint64_t al = MKDESC(xlo);
    const uint64_t bd = MKDESC(wbf);

    float4 pax[8], pbx[8];
    float ps;

    // prologue: load chunk 0 and store it
    ps = __ldg(sinv + (size_t)blockIdx.x * (KDIM / 128) + 0);
    {
        const float4* x4 = reinterpret_cast<const float4*>(xrow);
        const float4* w4 = reinterpret_cast<const float4*>(wrow);
#pragma unroll
        for (int j = 0; j < 8; ++j) { pax[j] = x4[j]; pbx[j] = w4[j]; }
    }
#pragma unroll
    for (int j = 0; j < 4; ++j) {
        const uint32_t sw = SWZ(rowb + (uint32_t)j * 16);
        float4 a0 = pax[2 * j], a1 = pax[2 * j + 1];
        a0.x *= ps; a0.y *= ps; a0.z *= ps; a0.w *= ps;
        a1.x *= ps; a1.y *= ps; a1.z *= ps; a1.w *= ps;
        uint32_t h0, h1, h2, h3, l0, l1, l2, l3;
        split2(a0.x, a0.y, h0, l0); split2(a0.z, a0.w, h1, l1);
        split2(a1.x, a1.y, h2, l2); split2(a1.z, a1.w, h3, l3);
        STS128(xhi + sw, h0, h1, h2, h3);
        STS128(xlo + sw, l0, l1, l2, l3);
        float4 b0 = pbx[2 * j], b1 = pbx[2 * j + 1];
        STS128(wbf + sw, pack_bf16x2(b0.x, b0.y), pack_bf16x2(b0.z, b0.w),
               pack_bf16x2(b1.x, b1.y), pack_bf16x2(b1.z, b1.w));
    }
    FENCE_ASYNC_SHARED();

    int ph = 0;

#pragma unroll 1
    for (int kc = 0; kc < NCHUNKS; ++kc) {
        __syncthreads();  // chunk kc stores visible before MMA reads

        if (wid == 0) {
            if (elect1()) {
#pragma unroll
                for (int ks = 0; ks < 4; ++ks)
                    mma_f16_ss(tmem_base, ah + ks * 2, bd + ks * 2, IDESC,
                               !(kc == 0 && ks == 0));
#pragma unroll
                for (int ks = 0; ks < 4; ++ks)
                    mma_f16_ss(tmem_base, al + ks * 2, bd + ks * 2, IDESC, true);
                TCGEN05_COMMIT(mbar);
            }
        }

        // prefetch chunk kc+1 (overlaps MMA execution)
        if (kc + 1 < NCHUNKS) {
            const float4* x4 = reinterpret_cast<const float4*>(xrow + (kc + 1) * KC);
            const float4* w4 = reinterpret_cast<const float4*>(wrow + (kc + 1) * KC);
            ps = __ldg(sinv + (size_t)blockIdx.x * (KDIM / 128) + ((kc + 1) >> 1));
#pragma unroll
            for (int j = 0; j < 8; ++j) { pax[j] = x4[j]; pbx[j] = w4[j]; }
        }

        MBARRIER_WAIT_PARITY(mbar, ph);   // MMA group for chunk kc complete
        ph ^= 1;

        if (kc + 1 < NCHUNKS) {
#pragma unroll
            for (int j = 0; j < 4; ++j) {
                const uint32_t sw = SWZ(rowb + (uint32_t)j * 16);
                float4 a0 = pax[2 * j], a1 = pax[2 * j + 1];
                a0.x *= ps; a0.y *= ps; a0.z *= ps; a0.w *= ps;
                a1.x *= ps; a1.y *= ps; a1.z *= ps; a1.w *= ps;
                uint32_t h0, h1, h2, h3, l0, l1, l2, l3;
                split2(a0.x, a0.y, h0, l0); split2(a0.z, a0.w, h1, l1);
                split2(a1.x, a1.y, h2, l2); split2(a1.z, a1.w, h3, l3);
                STS128(xhi + sw, h0, h1, h2, h3);
                STS128(xlo + sw, l0, l1, l2, l3);
                float4 b0 = pbx[2 * j], b1 = pbx[2 * j + 1];
                STS128(wbf + sw, pack_bf16x2(b0.x, b0.y), pack_bf16x2(b0.z, b0.w),
                       pack_bf16x2(b1.x, b1.y), pack_bf16x2(b1.z, b1.w));
            }
            FENCE_ASYNC_SHARED();
        }
    }

    TCGEN05_FENCE_AFTER();

    // bias tile into smem (operand buffer is dead now)
    float* bsh = reinterpret_cast<float*>(smem + (buf - smem_base));
    if (tid < TN) bsh[tid] = bias[n0 + tid];
    __syncthreads();

    if (wid < 4) {
        const size_t orow = (size_t)(m0 + wid * 32 + lid) * NDIM + n0;
#pragma unroll
        for (int cb = 0; cb < 4; ++cb) {
            uint32_t r[32];
            TCGEN05_LD_32X32B_X32(r, tmem_base + cb * 32);
            TCGEN05_WAIT_LD();
#pragma unroll
            for (int j = 0; j < 8; ++j) {
                float4 v;
                v.x = __uint_as_float(r[4 * j + 0]) + bsh[cb * 32 + 4 * j + 0];
                v.y = __uint_as_float(r[4 * j + 1]) + bsh[cb * 32 + 4 * j + 1];
                v.z = __uint_as_float(r[4 * j + 2]) + bsh[cb * 32 + 4 * j + 2];
                v.w = __uint_as_float(r[4 * j + 3]) + bsh[cb * 32 + 4 * j + 3];
                *reinterpret_cast<float4*>(out + orow + cb * 32 + 4 * j) = v;
            }
        }
    }

    __syncthreads();
    if (tid == 0) MBARRIER_INVAL(mbar);
    if (wid == 0) {
        TCGEN05_DEALLOC(tmem_base, 128);
    }
#endif  // TC_FEAT
}

// ==================== tf32 mma.sync fallback (proven R3, 887us) ====================

#define FKC 32
#define FNCH (KDIM / FKC)
#define FA_WORDS 4096
#define FB_WORDS 4096
#define FBUF_WORDS (FA_WORDS + FB_WORDS)
#define FSMEM_BYTES (2 * FBUF_WORDS * 4)

static __device__ __forceinline__ uint32_t f2tf32(float f) {
    uint32_t u;
    asm("cvt.rna.tf32.f32 %0, %1;" : "=r"(u) : "f"(f));
    return u;
}

static __device__ __forceinline__ void mma_tf32(float* c, const uint32_t* a,
                                                const uint32_t* b) {
    asm volatile(
        "mma.sync.aligned.m16n8k8.row.col.f32.tf32.tf32.f32 "
        "{%0,%1,%2,%3}, {%4,%5,%6,%7}, {%8,%9}, {%0,%1,%2,%3};"
        : "+f"(c[0]), "+f"(c[1]), "+f"(c[2]), "+f"(c[3])
        : "r"(a[0]), "r"(a[1]), "r"(a[2]), "r"(a[3]), "r"(b[0]), "r"(b[1]));
}

extern "C" __global__ void __launch_bounds__(256)
f8lin_fallback(const float* __restrict__ x, const float* __restrict__ w,
               const float* __restrict__ sinv, const float* __restrict__ bias,
               float* __restrict__ out) {
    if (g_tc_flag) return;

    extern __shared__ uint32_t fsm[];
    const int tid = threadIdx.x;
    const int warp = tid >> 5;
    const int lane = tid & 31;
    const int wm = warp >> 2;
    const int wn = warp & 3;

    const int n0 = blockIdx.x * 128;
    const int m0 = blockIdx.y * 128;

    const int k4 = tid & 7;
    const int rbase = tid >> 3;
    const int kstepW = k4 >> 1;

    const float* xp = x + (size_t)(m0 + rbase) * KDIM + k4 * 4;
    const float* wp = w + (size_t)(n0 + rbase) * KDIM + k4 * 4;

    uint32_t aoff[4], boff[4];
#pragma unroll
    for (int it = 0; it < 4; ++it) {
        int m = rbase + it * 32;
        aoff[it] = ((((m >> 4) * 4 + kstepW) * 4 + ((m >> 3) & 1) + 2 * (k4 & 1)) << 5)
                   + (((m & 7) ^ k4) << 2);
        int n = m;
        boff[it] = FA_WORDS
                   + ((((n >> 3) * 4 + kstepW) * 2 + (k4 & 1)) << 5)
                   + (((n & 7) ^ k4) << 2);
    }

    float acc[4][4][4];
#pragma unroll
    for (int i = 0; i < 4; ++i)
#pragma unroll
        for (int j = 0; j < 4; ++j)
#pragma unroll
            for (int r = 0; r < 4; ++r) acc[i][j][r] = 0.0f;

    float4 pax[4], pbx[4];
    float ps;

    ps = __ldg(sinv + (size_t)blockIdx.x * 32 + 0);
#pragma unroll
    for (int it = 0; it < 4; ++it) {
        pax[it] = *reinterpret_cast<const float4*>(xp + (size_t)it * 32 * KDIM);
        pbx[it] = *reinterpret_cast<const float4*>(wp + (size_t)it * 32 * KDIM);
    }
    {
        uint32_t* buf = fsm;
#pragma unroll
        for (int it = 0; it < 4; ++it) {
            float4 v = pax[it];
            uint4 t;
            t.x = f2tf32(v.x * ps); t.y = f2tf32(v.y * ps);
            t.z = f2tf32(v.z * ps); t.w = f2tf32(v.w * ps);
            *reinterpret_cast<uint4*>(buf + aoff[it]) = t;
            float4 u = pbx[it];
            uint4 s2;
            s2.x = f2tf32(u.x); s2.y = f2tf32(u.y);
            s2.z = f2tf32(u.z); s2.w = f2tf32(u.w);
            *reinterpret_cast<uint4*>(buf + boff[it]) = s2;
        }
    }
    __syncthreads();

#pragma unroll 1
    for (int kc = 0; kc < FNCH; ++kc) {
        if (kc + 1 < FNCH) {
            const float* xn = xp + (kc + 1) * FKC;
            const float* wn2 = wp + (kc + 1) * FKC;
            ps = __ldg(sinv + (size_t)blockIdx.x * 32 + ((kc + 1) >> 2));
#pragma unroll
            for (int it = 0; it < 4; ++it) {
                pax[it] = *reinterpret_cast<const float4*>(xn + (size_t)it * 32 * KDIM);
                pbx[it] = *reinterpret_cast<const float4*>(wn2 + (size_t)it * 32 * KDIM);
            }
        }

        const uint32_t* buf = fsm + (kc & 1) * FBUF_WORDS;
#pragma unroll
        for (int ks = 0; ks < 4; ++ks) {
            uint32_t afr[4][4], bfr[4][2];
#pragma unroll
            for (int mt = 0; mt < 4; ++mt) {
                int mtileC = wm * 4 + mt;
#pragma unroll
                for (int r = 0; r < 4; ++r) {
                    int k4c = ks * 2 + (r >> 1);
                    afr[mt][r] = buf[(((mtileC * 4 + ks) * 4 + r) << 5)
                                     + (lane ^ (k4c << 2))];
                }
            }
#pragma unroll
            for (int nt = 0; nt < 4; ++nt) {
                int ntileC = wn * 4 + nt;
#pragma unroll
                for (int r = 0; r < 2; ++r) {
                    int k4c = ks * 2 + r;
                    bfr[nt][r] = buf[FA_WORDS + (((ntileC * 4 + ks) * 2 + r) << 5)
                                     + (lane ^ (k4c << 2))];
                }
            }
#pragma unroll
            for (int mt = 0; mt < 4; ++mt)
#pragma unroll
                for (int nt = 0; nt < 4; ++nt)
                    mma_tf32(acc[mt][nt], afr[mt], bfr[nt]);
        }

        __syncthreads();
        if (kc + 1 < FNCH) {
            uint32_t* bufw = fsm + ((kc + 1) & 1) * FBUF_WORDS;
#pragma unroll
            for (int it = 0; it < 4; ++it) {
                float4 v = pax[it];
                uint4 t;
                t.x = f2tf32(v.x * ps); t.y = f2tf32(v.y * ps);
                t.z = f2tf32(v.z * ps); t.w = f2tf32(v.w * ps);
                *reinterpret_cast<uint4*>(bufw + aoff[it]) = t;
                float4 u = pbx[it];
                uint4 s2;
                s2.x = f2tf32(u.x); s2.y = f2tf32(u.y);
                s2.z = f2tf32(u.z); s2.w = f2tf32(u.w);
                *reinterpret_cast<uint4*>(bufw + boff[it]) = s2;
            }
            __syncthreads();
        }
    }

#pragma unroll
    for (int nt = 0; nt < 4; ++nt) {
        int col = n0 + wn * 32 + nt * 8 + (lane & 3) * 2;
        float2 bv = *reinterpret_cast<const float2*>(bias + col);
#pragma unroll
        for (int mt = 0; mt < 4; ++mt) {
            int row = m0 + wm * 64 + mt * 16 + (lane >> 2);
            float2 o0, o1;
            o0.x = acc[mt][nt][0] + bv.x;
            o0.y = acc[mt][nt][1] + bv.y;
            o1.x = acc[mt][nt][2] + bv.x;
            o1.y = acc[mt][nt][3] + bv.y;
            *reinterpret_cast<float2*>(out + (size_t)row * NDIM + col) = o0;
            *reinterpret_cast<float2*>(out + (size_t)(row + 8) * NDIM + col) = o1;
        }
    }
}

// ================================ launch =====================================

extern "C" void kernel_launch(void* const* d_in, const int* in_sizes, int n_in,
                              void* d_out, int out_size) {
    const float* x = (const float*)d_in[0];
    const float* w = (const float*)d_in[1];
    const float* s = (const float*)d_in[2];
    const float* b = (const float*)d_in[3];
    float* out = (float*)d_out;

    cudaFuncSetAttribute(f8lin_tcgen05,
                         cudaFuncAttributeMaxDynamicSharedMemorySize, SMEM_BYTES);
    cudaFuncSetAttribute(f8lin_fallback,
                         cudaFuncAttributeMaxDynamicSharedMemorySize, FSMEM_BYTES);

    dim3 grid(NDIM / 128, MDIM / 128);

    f8lin_probe<<<1, 1>>>();
    f8lin_tcgen05<<<grid, 256, SMEM_BYTES>>>(x, w, s, b, out);
    f8lin_fallback<<<grid, 256, FSMEM_BYTES>>>(x, w, s, b, out);
}

// round 9
// speedup vs baseline: 1.2169x; 1.2169x over previous
#include <cuda_runtime.h>
#include <cuda_bf16.h>
#include <cstdint>

// BlockedF8Linear: out[m,n] = sum_k x[m,k]*(w[n,k]*scale[n/128,k/128]) + bias[n]
// M = B*S = 4096, N = 4096, K = 4096.
//
// R9 = identical resubmit of R7/R8 (neither ran - GPU broker timeouts).
// tcgen05 bf16 hi/lo-split path (R6 base, PASSED @1352us, rel_err 5.9e-6) with
// the serialization removed: double-buffered SMEM + 2 mbarriers, exactly ONE
// commit outstanding. Per iter: issue MMA on buf A; wait only previous chunk's
// commit; convert+STS next chunk into buf B (overlaps MMA); prefetch LDGs.
// Kept from R6 (crash-avoidance): no relinquish, runtime 1024B-aligned base.
// Fallback: proven R3 tf32 kernel, self-gated on g_tc_flag.

#define KDIM 4096
#define NDIM 4096
#define MDIM 4096

#if defined(__CUDA_ARCH_FEAT_SM103_ALL) || defined(__CUDA_ARCH_FEAT_SM100_ALL)
#define TC_FEAT 1
#else
#define TC_FEAT 0
#endif

__device__ int g_tc_flag;

__global__ void f8lin_probe() {
#if TC_FEAT
    g_tc_flag = 1;
#else
    g_tc_flag = 0;
#endif
}

// ======================= tcgen05 path =======================

#define TM 128
#define TN 128
#define KC 64                         // one SW128 row of bf16 per chunk
#define NCHUNKS (KDIM / KC)           // 64
#define MAT_BYTES (TM * 128)          // 16384 per bf16 tile
#define BUF_STRIDE (3 * MAT_BYTES)    // x_hi, x_lo, w
#define SMEM_BYTES (1024 + 1024 + 2 * BUF_STRIDE)   // 100352

#define SWZ(b) ((b) ^ (((b) >> 3) & 0x70))

static __device__ __forceinline__ uint32_t smem_u32(const void* p) {
    uint32_t a;
    asm("{ .reg .u64 t; cvta.to.shared.u64 t, %1; cvt.u32.u64 %0, t; }"
        : "=r"(a) : "l"(p));
    return a;
}

#if TC_FEAT

// idesc kind::f16: dtype=F32(1<<4) atype=BF16(1<<7) btype=BF16(1<<10)
// N/8<<17 M/16<<24
static constexpr uint32_t IDESC =
    (1u << 4) | (1u << 7) | (1u << 10) | ((TN / 8u) << 17) | ((TM / 16u) << 24);

// SW128 K-major: layout=2, version=1, SBO=64, LBO=1
static constexpr uint64_t DESC_BASE =
    (uint64_t(2) << 61) | (uint64_t(1) << 46) | (uint64_t(64) << 32) | (uint64_t(1) << 16);
#define MKDESC(addr) (DESC_BASE | ((uint64_t)((addr) >> 4) & 0x3FFF))

static __device__ __forceinline__ uint32_t elect1() {
    uint32_t p;
    asm volatile(
        "{\n\t.reg .pred p;\n\t"
        "elect.sync _|p, 0xFFFFFFFF;\n\t"
        "selp.b32 %0, 1, 0, p;\n\t}"
        : "=r"(p));
    return p;
}

#define MBARRIER_INIT(addr, cnt) \
    asm volatile("mbarrier.init.shared.b64 [%0], %1;" :: "r"(addr), "r"(cnt) : "memory")
#define MBARRIER_INVAL(addr) \
    asm volatile("mbarrier.inval.shared.b64 [%0];" :: "r"(addr) : "memory")

#define MBARRIER_WAIT_PARITY(mbar_addr, parity) do {                                   \
    uint32_t _mbar = (uint32_t)(mbar_addr);                                            \
    uint32_t _par = (uint32_t)(parity);                                                \
    asm volatile(                                                                      \
        "{\n\t.reg .pred P1;\n\t"                                                      \
        "WAIT_LOOP_%=:\n\t"                                                            \
        "mbarrier.try_wait.parity.acquire.cta.shared::cta.b64 P1, [%0], %1, 0x989680;\n\t" \
        "@P1 bra.uni WAIT_DONE_%=;\n\t"                                                \
        "bra.uni WAIT_LOOP_%=;\n\t"                                                    \
        "WAIT_DONE_%=:\n\t}"                                                           \
        :: "r"(_mbar), "r"(_par) : "memory");                                          \
} while (0)

#define TCGEN05_ALLOC(sa, n) \
    asm volatile("tcgen05.alloc.cta_group::1.sync.aligned.shared::cta.b32 [%0], %1;" \
                 :: "r"((uint32_t)(sa)), "r"((uint32_t)(n)) : "memory")
#define TCGEN05_DEALLOC(tm, n) \
    asm volatile("tcgen05.dealloc.cta_group::1.sync.aligned.b32 %0, %1;" :: "r"(tm), "r"(n))
#define TCGEN05_COMMIT(mbar) \
    asm volatile("tcgen05.commit.cta_group::1.mbarrier::arrive::one.shared::cluster.b64 [%0];" \
                 :: "r"((uint32_t)(mbar)) : "memory")
#define TCGEN05_FENCE_AFTER() \
    asm volatile("tcgen05.fence::after_thread_sync;" ::: "memory")
#define TCGEN05_WAIT_LD() \
    asm volatile("tcgen05.wait::ld.sync.aligned;" ::: "memory")
#define FENCE_ASYNC_SHARED() \
    asm volatile("fence.proxy.async.shared::cta;" ::: "memory")

#define STS128(addr, r0, r1, r2, r3) \
    asm volatile("st.shared.v4.b32 [%0], {%1, %2, %3, %4};" \
                 :: "r"(addr), "r"(r0), "r"(r1), "r"(r2), "r"(r3) : "memory")

#define TCGEN05_LD_32X32B_X32(r, tmem_addr) \
    asm volatile( \
        "tcgen05.ld.sync.aligned.32x32b.x32.b32 " \
        "{%0, %1, %2, %3, %4, %5, %6, %7, " \
        " %8, %9, %10, %11, %12, %13, %14, %15, " \
        " %16, %17, %18, %19, %20, %21, %22, %23, " \
        " %24, %25, %26, %27, %28, %29, %30, %31}, [%32];" \
        : "=r"((r)[0]),  "=r"((r)[1]),  "=r"((r)[2]),  "=r"((r)[3]), \
          "=r"((r)[4]),  "=r"((r)[5]),  "=r"((r)[6]),  "=r"((r)[7]), \
          "=r"((r)[8]),  "=r"((r)[9]),  "=r"((r)[10]), "=r"((r)[11]), \
          "=r"((r)[12]), "=r"((r)[13]), "=r"((r)[14]), "=r"((r)[15]), \
          "=r"((r)[16]), "=r"((r)[17]), "=r"((r)[18]), "=r"((r)[19]), \
          "=r"((r)[20]), "=r"((r)[21]), "=r"((r)[22]), "=r"((r)[23]), \
          "=r"((r)[24]), "=r"((r)[25]), "=r"((r)[26]), "=r"((r)[27]), \
          "=r"((r)[28]), "=r"((r)[29]), "=r"((r)[30]), "=r"((r)[31]) \
        : "r"(tmem_addr))

static __device__ __forceinline__ void mma_f16_ss(
    uint32_t d_tmem, uint64_t a_desc, uint64_t b_desc, uint32_t idesc, bool acc) {
    uint32_t en = acc ? 1u : 0u;
    asm volatile(
        "{\n\t.reg .pred p;\n\t"
        "setp.ne.u32 p, %5, 0;\n\t"
        "tcgen05.mma.cta_group::1.kind::f16 [%0], %1, %2, %3, {%4, %4, %4, %4}, p;\n\t}"
        :: "r"(d_tmem), "l"(a_desc), "l"(b_desc), "r"(idesc), "r"(0u), "r"(en)
        : "memory");
}

static __device__ __forceinline__ void split2(float v0, float v1, uint32_t& hi, uint32_t& lo) {
    __nv_bfloat162 h = __floats2bfloat162_rn(v0, v1);
    float r0 = v0 - __bfloat162float(h.x);
    float r1 = v1 - __bfloat162float(h.y);
    __nv_bfloat162 l = __floats2bfloat162_rn(r0, r1);
    hi = *reinterpret_cast<uint32_t*>(&h);
    lo = *reinterpret_cast<uint32_t*>(&l);
}

static __device__ __forceinline__ uint32_t pack_bf16x2(float v0, float v1) {
    __nv_bfloat162 h = __floats2bfloat162_rn(v0, v1);
    return *reinterpret_cast<uint32_t*>(&h);
}

#endif  // TC_FEAT

extern "C" __global__ void __launch_bounds__(256) __cluster_dims__(1, 1, 1)
f8lin_tcgen05(const float* __restrict__ x, const float* __restrict__ w,
              const float* __restrict__ sinv, const float* __restrict__ bias,
              float* __restrict__ out) {
#if TC_FEAT
    extern __shared__ char smem[];
    const uint32_t smem_base = smem_u32(smem);
    const int tid = threadIdx.x;
    const int wid = tid >> 5;
    const int lid = tid & 31;

    const int n0 = blockIdx.x * TN;
    const int m0 = blockIdx.y * TM;

    const uint32_t mbar0 = smem_base + 8;
    const uint32_t mbar1 = smem_base + 16;
    // 1024B-aligned operand base (SW128 descriptor requirement)
    const uint32_t bufbase = (smem_base + 1024 + 1023) & ~1023u;

    if (wid == 0) {
        TCGEN05_ALLOC(smem_base, 128);
    }
    if (tid == 0) {
        MBARRIER_INIT(mbar0, 1);
        MBARRIER_INIT(mbar1, 1);
    }
    __syncthreads();
    uint32_t tmem_base;
    asm volatile("ld.shared.b32 %0, [%1];" : "=r"(tmem_base) : "r"(smem_base));

    // producer mapping: row = tid>>1 (0..127), k-half h = tid&1 (32 elems)
    const int row = tid >> 1;
    const int h = tid & 1;
    const float* xrow = x + (size_t)(m0 + row) * KDIM + h * 32;
    const float* wrow = w + (size_t)(n0 + row) * KDIM + h * 32;
    const uint32_t rowb = (uint32_t)row * 128 + (uint32_t)h * 64;

    float4 pax[8], pbx[8];
    float ps;

    // ---- prologue: chunk 0 -> buf0; chunk 1 -> regs ----
    ps = __ldg(sinv + (size_t)blockIdx.x * (KDIM / 128) + 0);
    {
        const float4* x4 = reinterpret_cast<const float4*>(xrow);
        const float4* w4 = reinterpret_cast<const float4*>(wrow);
#pragma unroll
        for (int j = 0; j < 8; ++j) { pax[j] = x4[j]; pbx[j] = w4[j]; }
    }
    {
        const uint32_t b0 = bufbase;
#pragma unroll
        for (int j = 0; j < 4; ++j) {
            const uint32_t sw = SWZ(rowb + (uint32_t)j * 16);
            float4 a0 = pax[2 * j], a1 = pax[2 * j + 1];
            a0.x *= ps; a0.y *= ps; a0.z *= ps; a0.w *= ps;
            a1.x *= ps; a1.y *= ps; a1.z *= ps; a1.w *= ps;
            uint32_t h0, h1, h2, h3, l0, l1, l2, l3;
            split2(a0.x, a0.y, h0, l0); split2(a0.z, a0.w, h1, l1);
            split2(a1.x, a1.y, h2, l2); split2(a1.z, a1.w, h3, l3);
            STS128(b0 + sw, h0, h1, h2, h3);
            STS128(b0 + MAT_BYTES + sw, l0, l1, l2, l3);
            float4 w0 = pbx[2 * j], w1 = pbx[2 * j + 1];
            STS128(b0 + 2 * MAT_BYTES + sw,
                   pack_bf16x2(w0.x, w0.y), pack_bf16x2(w0.z, w0.w),
                   pack_bf16x2(w1.x, w1.y), pack_bf16x2(w1.z, w1.w));
        }
    }
    FENCE_ASYNC_SHARED();
    // load chunk 1 into regs
    {
        const float4* x4 = reinterpret_cast<const float4*>(xrow + KC);
        const float4* w4 = reinterpret_cast<const float4*>(wrow + KC);
#pragma unroll
        for (int j = 0; j < 8; ++j) { pax[j] = x4[j]; pbx[j] = w4[j]; }
        ps = __ldg(sinv + (size_t)blockIdx.x * (KDIM / 128) + 0);  // chunk1 scale (kc=1 >>1 = 0)
    }

    int ph0 = 0, ph1 = 0;

#pragma unroll 1
    for (int kc = 0; kc < NCHUNKS; ++kc) {
        const uint32_t mybuf = bufbase + (uint32_t)(kc & 1) * BUF_STRIDE;

        __syncthreads();   // buf[kc&1] stores visible to async proxy readers

        // 1. issue MMAs for chunk kc + commit (do NOT wait)
        if (wid == 0) {
            const uint64_t ah = MKDESC(mybuf);
            const uint64_t al = MKDESC(mybuf + MAT_BYTES);
            const uint64_t bd = MKDESC(mybuf + 2 * MAT_BYTES);
            if (elect1()) {
#pragma unroll
                for (int ks = 0; ks < 4; ++ks)
                    mma_f16_ss(tmem_base, ah + ks * 2, bd + ks * 2, IDESC,
                               !(kc == 0 && ks == 0));
#pragma unroll
                for (int ks = 0; ks < 4; ++ks)
                    mma_f16_ss(tmem_base, al + ks * 2, bd + ks * 2, IDESC, true);
                TCGEN05_COMMIT((kc & 1) ? mbar1 : mbar0);
            }
        }

        // 2. wait for PREVIOUS chunk's MMAs (frees buf[(kc+1)&1])
        if (kc >= 1) {
            if ((kc & 1) == 1) { MBARRIER_WAIT_PARITY(mbar0, ph0); ph0 ^= 1; }
            else               { MBARRIER_WAIT_PARITY(mbar1, ph1); ph1 ^= 1; }
        }

        // 3. store chunk kc+1 (regs) into buf[(kc+1)&1]  (overlaps chunk kc MMA)
        if (kc + 1 < NCHUNKS) {
            const uint32_t obuf = bufbase + (uint32_t)((kc + 1) & 1) * BUF_STRIDE;
#pragma unroll
            for (int j = 0; j < 4; ++j) {
                const uint32_t sw = SWZ(rowb + (uint32_t)j * 16);
                float4 a0 = pax[2 * j], a1 = pax[2 * j + 1];
                a0.x *= ps; a0.y *= ps; a0.z *= ps; a0.w *= ps;
                a1.x *= ps; a1.y *= ps; a1.z *= ps; a1.w *= ps;
                uint32_t h0, h1, h2, h3, l0, l1, l2, l3;
                split2(a0.x, a0.y, h0, l0); split2(a0.z, a0.w, h1, l1);
                split2(a1.x, a1.y, h2, l2); split2(a1.z, a1.w, h3, l3);
                STS128(obuf + sw, h0, h1, h2, h3);
                STS128(obuf + MAT_BYTES + sw, l0, l1, l2, l3);
                float4 w0 = pbx[2 * j], w1 = pbx[2 * j + 1];
                STS128(obuf + 2 * MAT_BYTES + sw,
                       pack_bf16x2(w0.x, w0.y), pack_bf16x2(w0.z, w0.w),
                       pack_bf16x2(w1.x, w1.y), pack_bf16x2(w1.z, w1.w));
            }
            FENCE_ASYNC_SHARED();
        }

        // 4. prefetch chunk kc+2 into regs (latency hidden under next iter)
        if (kc + 2 < NCHUNKS) {
            const float4* x4 = reinterpret_cast<const float4*>(xrow + (kc + 2) * KC);
            const float4* w4 = reinterpret_cast<const float4*>(wrow + (kc + 2) * KC);
#pragma unroll
            for (int j = 0; j < 8; ++j) { pax[j] = x4[j]; pbx[j] = w4[j]; }
            ps = __ldg(sinv + (size_t)blockIdx.x * (KDIM / 128) + ((kc + 2) >> 1));
        }
    }

    // final: wait for chunk 63's commit (mbar1; 31 in-loop waits happened)
    MBARRIER_WAIT_PARITY(mbar1, ph1);
    TCGEN05_FENCE_AFTER();

    // bias tile into smem (operand buffers are dead)
    float* bsh = reinterpret_cast<float*>(smem + (bufbase - smem_base));
    if (tid < TN) bsh[tid] = bias[n0 + tid];
    __syncthreads();

    if (wid < 4) {
        const size_t orow = (size_t)(m0 + wid * 32 + lid) * NDIM + n0;
#pragma unroll
        for (int cb = 0; cb < 4; ++cb) {
            uint32_t r[32];
            TCGEN05_LD_32X32B_X32(r, tmem_base + cb * 32);
            TCGEN05_WAIT_LD();
#pragma unroll
            for (int j = 0; j < 8; ++j) {
                float4 v;
                v.x = __uint_as_float(r[4 * j + 0]) + bsh[cb * 32 + 4 * j + 0];
                v.y = __uint_as_float(r[4 * j + 1]) + bsh[cb * 32 + 4 * j + 1];
                v.z = __uint_as_float(r[4 * j + 2]) + bsh[cb * 32 + 4 * j + 2];
                v.w = __uint_as_float(r[4 * j + 3]) + bsh[cb * 32 + 4 * j + 3];
                *reinterpret_cast<float4*>(out + orow + cb * 32 + 4 * j) = v;
            }
        }
    }

    __syncthreads();
    if (tid == 0) { MBARRIER_INVAL(mbar0); MBARRIER_INVAL(mbar1); }
    if (wid == 0) {
        TCGEN05_DEALLOC(tmem_base, 128);
    }
#endif  // TC_FEAT
}

// ==================== tf32 mma.sync fallback (proven R3, 887us) ====================

#define FKC 32
#define FNCH (KDIM / FKC)
#define FA_WORDS 4096
#define FB_WORDS 4096
#define FBUF_WORDS (FA_WORDS + FB_WORDS)
#define FSMEM_BYTES (2 * FBUF_WORDS * 4)

static __device__ __forceinline__ uint32_t f2tf32(float f) {
    uint32_t u;
    asm("cvt.rna.tf32.f32 %0, %1;" : "=r"(u) : "f"(f));
    return u;
}

static __device__ __forceinline__ void mma_tf32(float* c, const uint32_t* a,
                                                const uint32_t* b) {
    asm volatile(
        "mma.sync.aligned.m16n8k8.row.col.f32.tf32.tf32.f32 "
        "{%0,%1,%2,%3}, {%4,%5,%6,%7}, {%8,%9}, {%0,%1,%2,%3};"
        : "+f"(c[0]), "+f"(c[1]), "+f"(c[2]), "+f"(c[3])
        : "r"(a[0]), "r"(a[1]), "r"(a[2]), "r"(a[3]), "r"(b[0]), "r"(b[1]));
}

extern "C" __global__ void __launch_bounds__(256)
f8lin_fallback(const float* __restrict__ x, const float* __restrict__ w,
               const float* __restrict__ sinv, const float* __restrict__ bias,
               float* __restrict__ out) {
    if (g_tc_flag) return;

    extern __shared__ uint32_t fsm[];
    const int tid = threadIdx.x;
    const int warp = tid >> 5;
    const int lane = tid & 31;
    const int wm = warp >> 2;
    const int wn = warp & 3;

    const int n0 = blockIdx.x * 128;
    const int m0 = blockIdx.y * 128;

    const int k4 = tid & 7;
    const int rbase = tid >> 3;
    const int kstepW = k4 >> 1;

    const float* xp = x + (size_t)(m0 + rbase) * KDIM + k4 * 4;
    const float* wp = w + (size_t)(n0 + rbase) * KDIM + k4 * 4;

    uint32_t aoff[4], boff[4];
#pragma unroll
    for (int it = 0; it < 4; ++it) {
        int m = rbase + it * 32;
        aoff[it] = ((((m >> 4) * 4 + kstepW) * 4 + ((m >> 3) & 1) + 2 * (k4 & 1)) << 5)
                   + (((m & 7) ^ k4) << 2);
        int n = m;
        boff[it] = FA_WORDS
                   + ((((n >> 3) * 4 + kstepW) * 2 + (k4 & 1)) << 5)
                   + (((n & 7) ^ k4) << 2);
    }

    float acc[4][4][4];
#pragma unroll
    for (int i = 0; i < 4; ++i)
#pragma unroll
        for (int j = 0; j < 4; ++j)
#pragma unroll
            for (int r = 0; r < 4; ++r) acc[i][j][r] = 0.0f;

    float4 pax[4], pbx[4];
    float ps;

    ps = __ldg(sinv + (size_t)blockIdx.x * 32 + 0);
#pragma unroll
    for (int it = 0; it < 4; ++it) {
        pax[it] = *reinterpret_cast<const float4*>(xp + (size_t)it * 32 * KDIM);
        pbx[it] = *reinterpret_cast<const float4*>(wp + (size_t)it * 32 * KDIM);
    }
    {
        uint32_t* buf = fsm;
#pragma unroll
        for (int it = 0; it < 4; ++it) {
            float4 v = pax[it];
            uint4 t;
            t.x = f2tf32(v.x * ps); t.y = f2tf32(v.y * ps);
            t.z = f2tf32(v.z * ps); t.w = f2tf32(v.w * ps);
            *reinterpret_cast<uint4*>(buf + aoff[it]) = t;
            float4 u = pbx[it];
            uint4 s2;
            s2.x = f2tf32(u.x); s2.y = f2tf32(u.y);
            s2.z = f2tf32(u.z); s2.w = f2tf32(u.w);
            *reinterpret_cast<uint4*>(buf + boff[it]) = s2;
        }
    }
    __syncthreads();

#pragma unroll 1
    for (int kc = 0; kc < FNCH; ++kc) {
        if (kc + 1 < FNCH) {
            const float* xn = xp + (kc + 1) * FKC;
            const float* wn2 = wp + (kc + 1) * FKC;
            ps = __ldg(sinv + (size_t)blockIdx.x * 32 + ((kc + 1) >> 2));
#pragma unroll
            for (int it = 0; it < 4; ++it) {
                pax[it] = *reinterpret_cast<const float4*>(xn + (size_t)it * 32 * KDIM);
                pbx[it] = *reinterpret_cast<const float4*>(wn2 + (size_t)it * 32 * KDIM);
            }
        }

        const uint32_t* buf = fsm + (kc & 1) * FBUF_WORDS;
#pragma unroll
        for (int ks = 0; ks < 4; ++ks) {
            uint32_t afr[4][4], bfr[4][2];
#pragma unroll
            for (int mt = 0; mt < 4; ++mt) {
                int mtileC = wm * 4 + mt;
#pragma unroll
                for (int r = 0; r < 4; ++r) {
                    int k4c = ks * 2 + (r >> 1);
                    afr[mt][r] = buf[(((mtileC * 4 + ks) * 4 + r) << 5)
                                     + (lane ^ (k4c << 2))];
                }
            }
#pragma unroll
            for (int nt = 0; nt < 4; ++nt) {
                int ntileC = wn * 4 + nt;
#pragma unroll
                for (int r = 0; r < 2; ++r) {
                    int k4c = ks * 2 + r;
                    bfr[nt][r] = buf[FA_WORDS + (((ntileC * 4 + ks) * 2 + r) << 5)
                                     + (lane ^ (k4c << 2))];
                }
            }
#pragma unroll
            for (int mt = 0; mt < 4; ++mt)
#pragma unroll
                for (int nt = 0; nt < 4; ++nt)
                    mma_tf32(acc[mt][nt], afr[mt], bfr[nt]);
        }

        __syncthreads();
        if (kc + 1 < FNCH) {
            uint32_t* bufw = fsm + ((kc + 1) & 1) * FBUF_WORDS;
#pragma unroll
            for (int it = 0; it < 4; ++it) {
                float4 v = pax[it];
                uint4 t;
                t.x = f2tf32(v.x * ps); t.y = f2tf32(v.y * ps);
                t.z = f2tf32(v.z * ps); t.w = f2tf32(v.w * ps);
                *reinterpret_cast<uint4*>(bufw + aoff[it]) = t;
                float4 u = pbx[it];
                uint4 s2;
                s2.x = f2tf32(u.x); s2.y = f2tf32(u.y);
                s2.z = f2tf32(u.z); s2.w = f2tf32(u.w);
                *reinterpret_cast<uint4*>(bufw + boff[it]) = s2;
            }
            __syncthreads();
        }
    }

#pragma unroll
    for (int nt = 0; nt < 4; ++nt) {
        int col = n0 + wn * 32 + nt * 8 + (lane & 3) * 2;
        float2 bv = *reinterpret_cast<const float2*>(bias + col);
#pragma unroll
        for (int mt = 0; mt < 4; ++mt) {
            int row = m0 + wm * 64 + mt * 16 + (lane >> 2);
            float2 o0, o1;
            o0.x = acc[mt][nt][0] + bv.x;
            o0.y = acc[mt][nt][1] + bv.y;
            o1.x = acc[mt][nt][2] + bv.x;
            o1.y = acc[mt][nt][3] + bv.y;
            *reinterpret_cast<float2*>(out + (size_t)row * NDIM + col) = o0;
            *reinterpret_cast<float2*>(out + (size_t)(row + 8) * NDIM + col) = o1;
        }
    }
}

// ================================ launch =====================================

extern "C" void kernel_launch(void* const* d_in, const int* in_sizes, int n_in,
                              void* d_out, int out_size) {
    const float* x = (const float*)d_in[0];
    const float* w = (const float*)d_in[1];
    const float* s = (const float*)d_in[2];
    const float* b = (const float*)d_in[3];
    float* out = (float*)d_out;

    cudaFuncSetAttribute(f8lin_tcgen05,
                         cudaFuncAttributeMaxDynamicSharedMemorySize, SMEM_BYTES);
    cudaFuncSetAttribute(f8lin_fallback,
                         cudaFuncAttributeMaxDynamicSharedMemorySize, FSMEM_BYTES);

    dim3 grid(NDIM / 128, MDIM / 128);

    f8lin_probe<<<1, 1>>>();
    f8lin_tcgen05<<<grid, 256, SMEM_BYTES>>>(x, w, s, b, out);
    f8lin_fallback<<<grid, 256, FSMEM_BYTES>>>(x, w, s, b, out);
}

// round 17
// speedup vs baseline: 2.1393x; 1.7580x over previous
#include <cuda_runtime.h>
#include <cuda_bf16.h>
#include <cstdint>

// BlockedF8Linear: out[m,n] = sum_k x[m,k]*(w[n,k]*scale[n/128,k/128]) + bias[n]
// M = B*S = 4096, N = 4096, K = 4096.
//
// R17 = identical resubmit of R10-R16 (none ran - GPU broker timeouts).
// Three-kernel plan:
//  prep_x: x -> xhi+xlo bf16 (exact split, residual 2^-17), pre-swizzled SW128
//          tiles [mt][kc][16KB].
//  prep_w: wdq = w * scale (scale is a pure function of W indices) -> whi+wlo
//          bf16 pre-swizzled tiles [nt][kc][16KB].
//  gemm:   pure-copy mainloop: cp.async 4x16KB tiles/chunk (no ALU, no regs),
//          12 tcgen05 MMAs/chunk (hh+hl+lh; lo*lo dropped, ~4e-6), 3-stage
//          pipeline, fp32 TMEM accum, LDTM+bias epilogue.
// tcgen05 encodings identical to R6/R9 (proven: rel_err 5.9e-6).

#define KDIM 4096
#define NDIM 4096
#define MDIM 4096

#if defined(__CUDA_ARCH_FEAT_SM103_ALL) || defined(__CUDA_ARCH_FEAT_SM100_ALL)
#define TC_FEAT 1
#else
#define TC_FEAT 0
#endif

#define TM 128
#define TN 128
#define KC 64                          // one SW128 row of bf16 per chunk
#define NCHUNKS (KDIM / KC)            // 64
#define NT (NDIM / TN)                 // 32
#define MT (MDIM / TM)                 // 32
#define TILE_BYTES 16384               // 128 rows x 128B (bf16 KC=64)

// Precomputed operand tiles, pre-swizzled (SW128) and tile-major.
__device__ __align__(1024) unsigned char g_xhi[MT][NCHUNKS][TILE_BYTES];
__device__ __align__(1024) unsigned char g_xlo[MT][NCHUNKS][TILE_BYTES];
__device__ __align__(1024) unsigned char g_whi[NT][NCHUNKS][TILE_BYTES];
__device__ __align__(1024) unsigned char g_wlo[NT][NCHUNKS][TILE_BYTES];

#define SWZ(b) ((b) ^ (((b) >> 3) & 0x70))

static __device__ __forceinline__ void split2(float v0, float v1, uint32_t& hi, uint32_t& lo) {
    __nv_bfloat162 h = __floats2bfloat162_rn(v0, v1);
    float r0 = v0 - __bfloat162float(h.x);
    float r1 = v1 - __bfloat162float(h.y);
    __nv_bfloat162 l = __floats2bfloat162_rn(r0, r1);
    hi = *reinterpret_cast<uint32_t*>(&h);
    lo = *reinterpret_cast<uint32_t*>(&l);
}

// ===================== prep kernels (plain CUDA, any arch) =====================
// One block per (tile, chunk): 256 threads; thread t handles row t>>1, half t&1.

extern "C" __global__ void __launch_bounds__(256)
prep_x_kernel(const float* __restrict__ x) {
    const int kc = blockIdx.x;
    const int mt = blockIdx.y;
    const int t = threadIdx.x;
    const int row = t >> 1;
    const int h = t & 1;

    const float4* src = reinterpret_cast<const float4*>(
        x + (size_t)(mt * TM + row) * KDIM + kc * KC + h * 32);
    unsigned char* dhi = g_xhi[mt][kc];
    unsigned char* dlo = g_xlo[mt][kc];
    const uint32_t rowb = (uint32_t)row * 128 + (uint32_t)h * 64;

#pragma unroll
    for (int j = 0; j < 4; ++j) {
        float4 a0 = src[2 * j];
        float4 a1 = src[2 * j + 1];
        uint4 hi, lo;
        split2(a0.x, a0.y, hi.x, lo.x);
        split2(a0.z, a0.w, hi.y, lo.y);
        split2(a1.x, a1.y, hi.z, lo.z);
        split2(a1.z, a1.w, hi.w, lo.w);
        const uint32_t sw = SWZ(rowb + (uint32_t)j * 16);
        *reinterpret_cast<uint4*>(dhi + sw) = hi;
        *reinterpret_cast<uint4*>(dlo + sw) = lo;
    }
}

extern "C" __global__ void __launch_bounds__(256)
prep_w_kernel(const float* __restrict__ w, const float* __restrict__ sinv) {
    const int kc = blockIdx.x;
    const int nt = blockIdx.y;
    const int t = threadIdx.x;
    const int row = t >> 1;
    const int h = t & 1;

    const float s = __ldg(sinv + (size_t)nt * (KDIM / 128) + (kc >> 1));
    const float4* src = reinterpret_cast<const float4*>(
        w + (size_t)(nt * TN + row) * KDIM + kc * KC + h * 32);
    unsigned char* dhi = g_whi[nt][kc];
    unsigned char* dlo = g_wlo[nt][kc];
    const uint32_t rowb = (uint32_t)row * 128 + (uint32_t)h * 64;

#pragma unroll
    for (int j = 0; j < 4; ++j) {
        float4 a0 = src[2 * j];
        float4 a1 = src[2 * j + 1];
        a0.x *= s; a0.y *= s; a0.z *= s; a0.w *= s;
        a1.x *= s; a1.y *= s; a1.z *= s; a1.w *= s;
        uint4 hi, lo;
        split2(a0.x, a0.y, hi.x, lo.x);
        split2(a0.z, a0.w, hi.y, lo.y);
        split2(a1.x, a1.y, hi.z, lo.z);
        split2(a1.z, a1.w, hi.w, lo.w);
        const uint32_t sw = SWZ(rowb + (uint32_t)j * 16);
        *reinterpret_cast<uint4*>(dhi + sw) = hi;
        *reinterpret_cast<uint4*>(dlo + sw) = lo;
    }
}

// =============================== GEMM kernel ==================================

#define NSTAGE 3
#define STAGE_BYTES (4 * TILE_BYTES)              // xhi,xlo,whi,wlo
#define SMEM_BYTES (2048 + NSTAGE * STAGE_BYTES)  // 198656

static __device__ __forceinline__ uint32_t smem_u32(const void* p) {
    uint32_t a;
    asm("{ .reg .u64 t; cvta.to.shared.u64 t, %1; cvt.u32.u64 %0, t; }"
        : "=r"(a) : "l"(p));
    return a;
}

#define CPASYNC16(saddr, gptr) \
    asm volatile("cp.async.cg.shared.global [%0], [%1], 16;" \
                 :: "r"(saddr), "l"(gptr) : "memory")
#define CPASYNC_COMMIT() asm volatile("cp.async.commit_group;" ::: "memory")
#define CPASYNC_WAIT1() asm volatile("cp.async.wait_group 1;" ::: "memory")

#if TC_FEAT

static constexpr uint32_t IDESC =
    (1u << 4) | (1u << 7) | (1u << 10) | ((TN / 8u) << 17) | ((TM / 16u) << 24);

static constexpr uint64_t DESC_BASE =
    (uint64_t(2) << 61) | (uint64_t(1) << 46) | (uint64_t(64) << 32) | (uint64_t(1) << 16);
#define MKDESC(addr) (DESC_BASE | ((uint64_t)((addr) >> 4) & 0x3FFF))

static __device__ __forceinline__ uint32_t elect1() {
    uint32_t p;
    asm volatile(
        "{\n\t.reg .pred p;\n\t"
        "elect.sync _|p, 0xFFFFFFFF;\n\t"
        "selp.b32 %0, 1, 0, p;\n\t}"
        : "=r"(p));
    return p;
}

#define MBARRIER_INIT(addr, cnt) \
    asm volatile("mbarrier.init.shared.b64 [%0], %1;" :: "r"(addr), "r"(cnt) : "memory")
#define MBARRIER_INVAL(addr) \
    asm volatile("mbarrier.inval.shared.b64 [%0];" :: "r"(addr) : "memory")

#define MBARRIER_WAIT_PARITY(mbar_addr, parity) do {                                   \
    uint32_t _mbar = (uint32_t)(mbar_addr);                                            \
    uint32_t _par = (uint32_t)(parity);                                                \
    asm volatile(                                                                      \
        "{\n\t.reg .pred P1;\n\t"                                                      \
        "WAIT_LOOP_%=:\n\t"                                                            \
        "mbarrier.try_wait.parity.acquire.cta.shared::cta.b64 P1, [%0], %1, 0x989680;\n\t" \
        "@P1 bra.uni WAIT_DONE_%=;\n\t"                                                \
        "bra.uni WAIT_LOOP_%=;\n\t"                                                    \
        "WAIT_DONE_%=:\n\t}"                                                           \
        :: "r"(_mbar), "r"(_par) : "memory");                                          \
} while (0)

#define TCGEN05_ALLOC(sa, n) \
    asm volatile("tcgen05.alloc.cta_group::1.sync.aligned.shared::cta.b32 [%0], %1;" \
                 :: "r"((uint32_t)(sa)), "r"((uint32_t)(n)) : "memory")
#define TCGEN05_DEALLOC(tm, n) \
    asm volatile("tcgen05.dealloc.cta_group::1.sync.aligned.b32 %0, %1;" :: "r"(tm), "r"(n))
#define TCGEN05_COMMIT(mbar) \
    asm volatile("tcgen05.commit.cta_group::1.mbarrier::arrive::one.shared::cluster.b64 [%0];" \
                 :: "r"((uint32_t)(mbar)) : "memory")
#define TCGEN05_FENCE_AFTER() \
    asm volatile("tcgen05.fence::after_thread_sync;" ::: "memory")
#define TCGEN05_WAIT_LD() \
    asm volatile("tcgen05.wait::ld.sync.aligned;" ::: "memory")
#define FENCE_ASYNC_SHARED() \
    asm volatile("fence.proxy.async.shared::cta;" ::: "memory")

#define TCGEN05_LD_32X32B_X32(r, tmem_addr) \
    asm volatile( \
        "tcgen05.ld.sync.aligned.32x32b.x32.b32 " \
        "{%0, %1, %2, %3, %4, %5, %6, %7, " \
        " %8, %9, %10, %11, %12, %13, %14, %15, " \
        " %16, %17, %18, %19, %20, %21, %22, %23, " \
        " %24, %25, %26, %27, %28, %29, %30, %31}, [%32];" \
        : "=r"((r)[0]),  "=r"((r)[1]),  "=r"((r)[2]),  "=r"((r)[3]), \
          "=r"((r)[4]),  "=r"((r)[5]),  "=r"((r)[6]),  "=r"((r)[7]), \
          "=r"((r)[8]),  "=r"((r)[9]),  "=r"((r)[10]), "=r"((r)[11]), \
          "=r"((r)[12]), "=r"((r)[13]), "=r"((r)[14]), "=r"((r)[15]), \
          "=r"((r)[16]), "=r"((r)[17]), "=r"((r)[18]), "=r"((r)[19]), \
          "=r"((r)[20]), "=r"((r)[21]), "=r"((r)[22]), "=r"((r)[23]), \
          "=r"((r)[24]), "=r"((r)[25]), "=r"((r)[26]), "=r"((r)[27]), \
          "=r"((r)[28]), "=r"((r)[29]), "=r"((r)[30]), "=r"((r)[31]) \
        : "r"(tmem_addr))

static __device__ __forceinline__ void mma_f16_ss(
    uint32_t d_tmem, uint64_t a_desc, uint64_t b_desc, uint32_t idesc, bool acc) {
    uint32_t en = acc ? 1u : 0u;
    asm volatile(
        "{\n\t.reg .pred p;\n\t"
        "setp.ne.u32 p, %5, 0;\n\t"
        "tcgen05.mma.cta_group::1.kind::f16 [%0], %1, %2, %3, {%4, %4, %4, %4}, p;\n\t}"
        :: "r"(d_tmem), "l"(a_desc), "l"(b_desc), "r"(idesc), "r"(0u), "r"(en)
        : "memory");
}

#endif  // TC_FEAT

// copy one chunk's 4 tiles into a stage: thread t copies bytes [t*64, t*64+64)
// of each tile with 4 cp.async.
static __device__ __forceinline__ void stage_copy(
    uint32_t sbase, int mt, int nt, int kc, int t) {
#if TC_FEAT
    const unsigned char* sx_hi = g_xhi[mt][kc] + t * 64;
    const unsigned char* sx_lo = g_xlo[mt][kc] + t * 64;
    const unsigned char* sw_hi = g_whi[nt][kc] + t * 64;
    const unsigned char* sw_lo = g_wlo[nt][kc] + t * 64;
    const uint32_t d = sbase + t * 64;
#pragma unroll
    for (int i = 0; i < 4; ++i) {
        CPASYNC16(d + i * 16, sx_hi + i * 16);
        CPASYNC16(d + TILE_BYTES + i * 16, sx_lo + i * 16);
        CPASYNC16(d + 2 * TILE_BYTES + i * 16, sw_hi + i * 16);
        CPASYNC16(d + 3 * TILE_BYTES + i * 16, sw_lo + i * 16);
    }
    CPASYNC_COMMIT();
#endif
}

extern "C" __global__ void __launch_bounds__(256) __cluster_dims__(1, 1, 1)
f8lin_gemm(const float* __restrict__ bias, float* __restrict__ out) {
#if TC_FEAT
    extern __shared__ char smem[];
    const uint32_t smem_base = smem_u32(smem);
    const int tid = threadIdx.x;
    const int wid = tid >> 5;
    const int lid = tid & 31;

    const int nt = blockIdx.x;
    const int mt = blockIdx.y;
    const int n0 = nt * TN;
    const int m0 = mt * TM;

    const uint32_t mb0 = smem_base + 8;
    const uint32_t mb1 = smem_base + 16;
    const uint32_t mb2 = smem_base + 24;
    const uint32_t bufbase = (smem_base + 1024 + 1023) & ~1023u;

    if (wid == 0) {
        TCGEN05_ALLOC(smem_base, 128);
    }
    if (tid == 0) {
        MBARRIER_INIT(mb0, 1);
        MBARRIER_INIT(mb1, 1);
        MBARRIER_INIT(mb2, 1);
    }
    __syncthreads();
    uint32_t tmem_base;
    asm volatile("ld.shared.b32 %0, [%1];" : "=r"(tmem_base) : "r"(smem_base));

    // prologue: chunks 0,1 into stages 0,1 (two cp.async groups)
    stage_copy(bufbase, mt, nt, 0, tid);
    stage_copy(bufbase + STAGE_BYTES, mt, nt, 1, tid);

    int p0 = 0, p1 = 0, p2 = 0;
    int scur = 0;  // kc % 3

#pragma unroll 1
    for (int kc = 0; kc < NCHUNKS; ++kc) {
        const uint32_t sb = bufbase + (uint32_t)scur * STAGE_BYTES;

        // chunk kc's copies complete (<=1 newer group may pend)
        CPASYNC_WAIT1();
        __syncthreads();
        FENCE_ASYNC_SHARED();

        // issue 12 MMAs (hh, hl, lh per K-step) + commit to mbar[scur]
        if (wid == 0) {
            const uint64_t axh = MKDESC(sb);
            const uint64_t axl = MKDESC(sb + TILE_BYTES);
            const uint64_t bwh = MKDESC(sb + 2 * TILE_BYTES);
            const uint64_t bwl = MKDESC(sb + 3 * TILE_BYTES);
            if (elect1()) {
#pragma unroll
                for (int ks = 0; ks < 4; ++ks) {
                    mma_f16_ss(tmem_base, axh + ks * 2, bwh + ks * 2, IDESC,
                               !(kc == 0 && ks == 0));
                    mma_f16_ss(tmem_base, axh + ks * 2, bwl + ks * 2, IDESC, true);
                    mma_f16_ss(tmem_base, axl + ks * 2, bwh + ks * 2, IDESC, true);
                }
                if (scur == 0)      TCGEN05_COMMIT(mb0);
                else if (scur == 1) TCGEN05_COMMIT(mb1);
                else                TCGEN05_COMMIT(mb2);
            }
        }

        // free stage (kc-1)%3 by waiting MMA(kc-1), then prefetch chunk kc+2 into it
        if (kc >= 1) {
            const int sm1 = (scur == 0) ? 2 : scur - 1;
            if (sm1 == 0)      { MBARRIER_WAIT_PARITY(mb0, p0); p0 ^= 1; }
            else if (sm1 == 1) { MBARRIER_WAIT_PARITY(mb1, p1); p1 ^= 1; }
            else               { MBARRIER_WAIT_PARITY(mb2, p2); p2 ^= 1; }
            if (kc + 2 < NCHUNKS)
                stage_copy(bufbase + (uint32_t)sm1 * STAGE_BYTES, mt, nt, kc + 2, tid);
        } else {
            // kc==0: stage 2 is virgin; prefetch chunk 2 without any wait
            stage_copy(bufbase + 2u * STAGE_BYTES, mt, nt, 2, tid);
        }

        scur = (scur == 2) ? 0 : scur + 1;
    }

    // last chunk 63 committed on stage 63%3 == 0
    MBARRIER_WAIT_PARITY(mb0, p0);
    TCGEN05_FENCE_AFTER();

    float* bsh = reinterpret_cast<float*>(smem + (bufbase - smem_base));
    if (tid < TN) bsh[tid] = bias[n0 + tid];
    __syncthreads();

    if (wid < 4) {
        const size_t orow = (size_t)(m0 + wid * 32 + lid) * NDIM + n0;
#pragma unroll
        for (int cb = 0; cb < 4; ++cb) {
            uint32_t r[32];
            TCGEN05_LD_32X32B_X32(r, tmem_base + cb * 32);
            TCGEN05_WAIT_LD();
#pragma unroll
            for (int j = 0; j < 8; ++j) {
                float4 v;
                v.x = __uint_as_float(r[4 * j + 0]) + bsh[cb * 32 + 4 * j + 0];
                v.y = __uint_as_float(r[4 * j + 1]) + bsh[cb * 32 + 4 * j + 1];
                v.z = __uint_as_float(r[4 * j + 2]) + bsh[cb * 32 + 4 * j + 2];
                v.w = __uint_as_float(r[4 * j + 3]) + bsh[cb * 32 + 4 * j + 3];
                *reinterpret_cast<float4*>(out + orow + cb * 32 + 4 * j) = v;
            }
        }
    }

    __syncthreads();
    if (tid == 0) { MBARRIER_INVAL(mb0); MBARRIER_INVAL(mb1); MBARRIER_INVAL(mb2); }
    if (wid == 0) {
        TCGEN05_DEALLOC(tmem_base, 128);
    }
#endif  // TC_FEAT
}

// ================================ launch =====================================

extern "C" void kernel_launch(void* const* d_in, const int* in_sizes, int n_in,
                              void* d_out, int out_size) {
    const float* x = (const float*)d_in[0];
    const float* w = (const float*)d_in[1];
    const float* s = (const float*)d_in[2];
    const float* b = (const float*)d_in[3];
    float* out = (float*)d_out;

    cudaFuncSetAttribute(f8lin_gemm,
                         cudaFuncAttributeMaxDynamicSharedMemorySize, SMEM_BYTES);

    dim3 pgrid(NCHUNKS, MT);  // 64 x 32
    prep_x_kernel<<<pgrid, 256>>>(x);
    prep_w_kernel<<<pgrid, 256>>>(w, s);

    dim3 grid(NT, MT);  // x fastest over N-tiles -> W hot in L2
    f8lin_gemm<<<grid, 256, SMEM_BYTES>>>(b, out);
}